// round 7
// baseline (speedup 1.0000x reference)
#include <cuda_runtime.h>

#define DIM   100
#define NW    39
#define NH    4
#define NBLK  4800
#define NTHR  256
#define NWARP 8
#define NQ    25          // float4 chunks per 100-float row
#define RPW   5           // rows per warp (ceil(39/8))

__global__ __launch_bounds__(NTHR, 4)
void tse_kernel(const float* __restrict__ x,
                const float* __restrict__ w_att,
                const float* __restrict__ b_att,
                float* __restrict__ out)
{
    __shared__ __align__(16) float4 sp4[NWARP * NH * NQ];   // partials (12.8 KB)
    __shared__ float sz[NWARP * NH];                        // per-warp Z partials

    const int tid  = threadIdx.x;
    const int warp = tid >> 5;
    const int lane = tid & 31;
    const int bid  = blockIdx.x;
    const float* __restrict__ xb = x + bid * (40 * DIM);
    const bool act = (lane < NQ);
    const int g = lane >> 3;            // this lane's head group (0..3)

    // ---- register-resident params ----
    float4 t4 = make_float4(0.f, 0.f, 0.f, 0.f);
    float4 wa4[NH], ba4[NH];
    #pragma unroll
    for (int h = 0; h < NH; h++) {
        wa4[h] = make_float4(0.f, 0.f, 0.f, 0.f);
        ba4[h] = make_float4(0.f, 0.f, 0.f, 0.f);
    }
    if (act) {
        t4 = reinterpret_cast<const float4*>(xb)[lane];
        #pragma unroll
        for (int h = 0; h < NH; h++) {
            wa4[h] = reinterpret_cast<const float4*>(w_att + h * DIM)[lane];
            ba4[h] = reinterpret_cast<const float4*>(b_att + h * DIM)[lane];
        }
    }

    const float* __restrict__ rp = xb + DIM + 4 * lane;

    // relative-order accumulators: accR[j] belongs to head (g ^ j)
    float4 accR[NH];
    #pragma unroll
    for (int j = 0; j < NH; j++) accR[j] = make_float4(0.f, 0.f, 0.f, 0.f);
    float zacc = 0.f;

    // ---- single fused loop over this warp's rows ----
    #pragma unroll
    for (int k = 0; k < RPW; k++) {
        const int n = warp + k * NWARP;
        float4 w4 = make_float4(0.f, 0.f, 0.f, 0.f);
        if (act && n < NW)
            w4 = *reinterpret_cast<const float4*>(rp + n * DIM);

        // scores for all 4 heads at this lane's 4 d-slots
        float a[NH];
        #pragma unroll
        for (int h = 0; h < NH; h++) {
            float p, s;
            p = fmaf(w4.x, wa4[h].x, ba4[h].x); p = fmaxf(p, 0.3f * p); s = t4.x * p;
            p = fmaf(w4.y, wa4[h].y, ba4[h].y); p = fmaxf(p, 0.3f * p); s = fmaf(t4.y, p, s);
            p = fmaf(w4.z, wa4[h].z, ba4[h].z); p = fmaxf(p, 0.3f * p); s = fmaf(t4.z, p, s);
            p = fmaf(w4.w, wa4[h].w, ba4[h].w); p = fmaxf(p, 0.3f * p); s = fmaf(t4.w, p, s);
            a[h] = s;
        }

        // packed reduction: group 0 (lanes 0-7) -> h0 sum, group 1 -> h1, etc.
        // butterfly leaves the group total in EVERY lane of the group.
        const bool lo = (lane < 16);
        float xv = __shfl_xor_sync(0xffffffffu, lo ? a[2] : a[0], 16);
        float yv = __shfl_xor_sync(0xffffffffu, lo ? a[3] : a[1], 16);
        float u0 = (lo ? a[0] : a[2]) + xv;
        float u1 = (lo ? a[1] : a[3]) + yv;
        const bool b3 = (lane & 8) != 0;
        float zv = __shfl_xor_sync(0xffffffffu, b3 ? u0 : u1, 8);
        float t  = (b3 ? u1 : u0) + zv;
        t += __shfl_xor_sync(0xffffffffu, t, 4);
        t += __shfl_xor_sync(0xffffffffu, t, 2);
        t += __shfl_xor_sync(0xffffffffu, t, 1);

        // e for own head-group; zero invalid rows BEFORE broadcasting
        float e0 = __expf(t);
        if (n >= NW) e0 = 0.f;
        const float e1 = __shfl_xor_sync(0xffffffffu, e0, 8);    // head g^1
        const float e2 = __shfl_xor_sync(0xffffffffu, e0, 16);   // head g^2
        const float e3 = __shfl_xor_sync(0xffffffffu, e1, 16);   // head g^3

        // accumulate weighted rows (w4 still live in registers)
        accR[0].x = fmaf(e0, w4.x, accR[0].x); accR[0].y = fmaf(e0, w4.y, accR[0].y);
        accR[0].z = fmaf(e0, w4.z, accR[0].z); accR[0].w = fmaf(e0, w4.w, accR[0].w);
        accR[1].x = fmaf(e1, w4.x, accR[1].x); accR[1].y = fmaf(e1, w4.y, accR[1].y);
        accR[1].z = fmaf(e1, w4.z, accR[1].z); accR[1].w = fmaf(e1, w4.w, accR[1].w);
        accR[2].x = fmaf(e2, w4.x, accR[2].x); accR[2].y = fmaf(e2, w4.y, accR[2].y);
        accR[2].z = fmaf(e2, w4.z, accR[2].z); accR[2].w = fmaf(e2, w4.w, accR[2].w);
        accR[3].x = fmaf(e3, w4.x, accR[3].x); accR[3].y = fmaf(e3, w4.y, accR[3].y);
        accR[3].z = fmaf(e3, w4.z, accR[3].z); accR[3].w = fmaf(e3, w4.w, accR[3].w);
        zacc += e0;
    }

    // ---- per-warp partials (remap relative j -> absolute head g^j) ----
    if (act) {
        #pragma unroll
        for (int j = 0; j < NH; j++) {
            const int h = g ^ j;
            sp4[(warp * NH + h) * NQ + lane] = accR[j];
        }
    }
    if ((lane & 7) == 0) sz[warp * NH + g] = zacc;
    __syncthreads();

    // ---- cross-warp reduce + normalize + coalesced float4 store ----
    if (tid < NH * NQ) {
        const int h = tid / NQ;
        const int i = tid - h * NQ;
        float4 v = sp4[h * NQ + i];
        float  Z = sz[h];
        #pragma unroll
        for (int w = 1; w < NWARP; w++) {
            const float4 p = sp4[(w * NH + h) * NQ + i];
            v.x += p.x; v.y += p.y; v.z += p.z; v.w += p.w;
            Z += sz[w * NH + h];
        }
        const float si = 1.f / Z;
        v.x *= si; v.y *= si; v.z *= si; v.w *= si;
        reinterpret_cast<float4*>(out + bid * (NH * DIM))[tid] = v;
    }
}

extern "C" void kernel_launch(void* const* d_in, const int* in_sizes, int n_in,
                              void* d_out, int out_size)
{
    const float* x     = (const float*)d_in[0];
    const float* w_att = (const float*)d_in[1];
    const float* b_att = (const float*)d_in[2];
    float* out = (float*)d_out;
    tse_kernel<<<NBLK, NTHR>>>(x, w_att, b_att, out);
}